// round 1
// baseline (speedup 1.0000x reference)
#include <cuda_runtime.h>
#include <math.h>

#define NPTS 262144
#define NS1 4096
#define NS2 128
#define PADN 64
#define F_IN 11
#define H1 128
#define H2 256
#define H3 512
#define CC 384
#define PH 128

// ---------------- scratch (static device globals; no allocation) ----------------
__device__ float    d_t1[NPTS * H1];                 // 134 MB
__device__ float    d_f[NPTS * H2];                  // 268 MB
__device__ float    d_g[NS1 * H2];                   // 4 MB
__device__ unsigned d_genc[NS1 * H2];                // 4 MB
__device__ float    d_h1[(size_t)NPTS * H3];         // 536 MB
__device__ unsigned d_tokenc[NS1 * CC];              // 6 MB

// ------------- monotonic float<->uint encoding for atomic max -------------
__device__ __forceinline__ unsigned encf(float x) {
    unsigned u = __float_as_uint(x);
    return (u & 0x80000000u) ? ~u : (u | 0x80000000u);
}
__device__ __forceinline__ float decf(unsigned u) {
    return (u & 0x80000000u) ? __uint_as_float(u & 0x7FFFFFFFu)
                             : __uint_as_float(~u);
}
#define NEG_INF_ENC 0x007FFFFFu   // encf(-inf)

// ---------------- kernel: zero output + init encoded max buffers ----------------
__global__ void k_pre(float* __restrict__ out, int n) {
    int i = blockIdx.x * blockDim.x + threadIdx.x;
    int stride = gridDim.x * blockDim.x;
    for (int j = i; j < n; j += stride) out[j] = 0.0f;
    if (i < NS1 * H2) d_genc[i] = NEG_INF_ENC;
    if (i < NS1 * CC) d_tokenc[i] = NEG_INF_ENC;
}

// ---------------- kernel: t1 = X @ W1 + b1  ([N,11] @ [11,128]) ----------------
__global__ void k_mlp1(const float* __restrict__ X,
                       const float* __restrict__ W1,
                       const float* __restrict__ b1) {
    int k = threadIdx.x;            // 0..127 output column
    float w[F_IN];
#pragma unroll
    for (int j = 0; j < F_IN; j++) w[j] = W1[j * H1 + k];
    float bb = b1[k];
    int p0 = blockIdx.x * 32;
#pragma unroll 4
    for (int p = p0; p < p0 + 32; p++) {
        float acc = bb;
#pragma unroll
        for (int j = 0; j < F_IN; j++) acc = fmaf(X[p * F_IN + j], w[j], acc);
        d_t1[p * H1 + k] = acc;
    }
}

// ---------------- kernel: decode g_enc -> g (float) ----------------
__global__ void k_dec_g() {
    int i = blockIdx.x * blockDim.x + threadIdx.x;
    if (i < NS1 * H2) d_g[i] = decf(d_genc[i]);
}

// ---------------- tiled SGEMM, 128x128x16, 8x8 per thread, 256 threads ----------------
// MODE 0: A = d_t1 [N,128], B = W2 [128,256], epilogue: +b2, store d_f, atomic segmax -> d_genc
// MODE 1: A = gather(concat(g[sid], f)) [N,512], B = W3 [512,512], epilogue: +b3, relu, store d_h1
// MODE 2: A = d_h1 [N,512], B = W4 [512,384], epilogue: +b4, atomic segmax -> d_tokenc (no store)
#define BM 128
#define BN 128
#define BK 16
#define TM 8
#define TN 8

template <int MODE>
__global__ void __launch_bounds__(256)
k_gemm(const float* __restrict__ B, const float* __restrict__ bias,
       const int* __restrict__ idx10) {
    constexpr int K  = (MODE == 0) ? H1 : H3;
    constexpr int NN = (MODE == 0) ? H2 : ((MODE == 1) ? H3 : CC);

    __shared__ float As[BK][BM + 4];
    __shared__ float Bs[BK][BN];
    __shared__ int   s_sid[BM];

    int tid  = threadIdx.x;
    int row0 = blockIdx.y * BM;
    int col0 = blockIdx.x * BN;

    if (tid < BM) s_sid[tid] = idx10[row0 + tid];
    __syncthreads();

    float acc[TM][TN];
#pragma unroll
    for (int i = 0; i < TM; i++)
#pragma unroll
        for (int j = 0; j < TN; j++) acc[i][j] = 0.0f;

    const int ty = tid >> 4;   // 0..15 -> row group
    const int tx = tid & 15;   // 0..15 -> col group

    for (int k0 = 0; k0 < K; k0 += BK) {
        // ---- load A tile (BMxBK) as 512 float4s, 2 per thread ----
#pragma unroll
        for (int q = tid; q < 512; q += 256) {
            int r    = q >> 2;       // row within tile
            int c4   = q & 3;        // float4 column within BK
            int gcol = k0 + c4 * 4;
            float4 v;
            if (MODE == 1) {
                if (gcol < H2)
                    v = *(const float4*)&d_g[s_sid[r] * H2 + gcol];
                else
                    v = *(const float4*)&d_f[(size_t)(row0 + r) * H2 + (gcol - H2)];
            } else if (MODE == 0) {
                v = *(const float4*)&d_t1[(size_t)(row0 + r) * K + gcol];
            } else {
                v = *(const float4*)&d_h1[(size_t)(row0 + r) * K + gcol];
            }
            As[c4 * 4 + 0][r] = v.x;
            As[c4 * 4 + 1][r] = v.y;
            As[c4 * 4 + 2][r] = v.z;
            As[c4 * 4 + 3][r] = v.w;
        }
        // ---- load B tile (BKxBN) ----
#pragma unroll
        for (int q = tid; q < 512; q += 256) {
            int r  = q >> 5;         // row within BK
            int c4 = q & 31;         // float4 column within BN
            float4 v = *(const float4*)&B[(k0 + r) * NN + col0 + c4 * 4];
            *(float4*)&Bs[r][c4 * 4] = v;
        }
        __syncthreads();

#pragma unroll
        for (int k = 0; k < BK; k++) {
            float a[TM], b[TN];
            *(float4*)&a[0] = *(const float4*)&As[k][ty * TM];
            *(float4*)&a[4] = *(const float4*)&As[k][ty * TM + 4];
            *(float4*)&b[0] = *(const float4*)&Bs[k][tx * TN];
            *(float4*)&b[4] = *(const float4*)&Bs[k][tx * TN + 4];
#pragma unroll
            for (int i = 0; i < TM; i++)
#pragma unroll
                for (int j = 0; j < TN; j++)
                    acc[i][j] = fmaf(a[i], b[j], acc[i][j]);
        }
        __syncthreads();
    }

    // ---- epilogue ----
#pragma unroll
    for (int i = 0; i < TM; i++) {
        int r    = ty * TM + i;
        int grow = row0 + r;
        int sid  = s_sid[r];
#pragma unroll
        for (int j = 0; j < TN; j++) {
            int gcol = col0 + tx * TN + j;
            float v  = acc[i][j] + bias[gcol];
            if (MODE == 0) {
                d_f[(size_t)grow * H2 + gcol] = v;
                atomicMax(&d_genc[sid * H2 + gcol], encf(v));
            } else if (MODE == 1) {
                v = fmaxf(v, 0.0f);
                d_h1[(size_t)grow * H3 + gcol] = v;
            } else {
                atomicMax(&d_tokenc[sid * CC + gcol], encf(v));
            }
        }
    }
}

// ---------------- kernel: pos embed + rank + scatter both outputs ----------------
__global__ void k_tail(const float* __restrict__ spc,
                       const float* __restrict__ P1, const float* __restrict__ pb1,
                       const float* __restrict__ P2, const float* __restrict__ pb2,
                       const int* __restrict__ idx21,
                       float* __restrict__ out) {
    int i   = blockIdx.x;      // superpoint-1 index
    int tid = threadIdx.x;     // 128 threads
    __shared__ float ph[PH];
    __shared__ int s_start;

    if (tid == 0) {
        int v = idx21[i];
        int lo = 0, hi = NS1;
        while (lo < hi) {
            int mid = (lo + hi) >> 1;
            if (idx21[mid] < v) lo = mid + 1; else hi = mid;
        }
        s_start = lo;
    }

    float c0 = spc[i * 3 + 0], c1 = spc[i * 3 + 1], c2 = spc[i * 3 + 2];
    float x = fmaf(c0, P1[tid], fmaf(c1, P1[PH + tid], fmaf(c2, P1[2 * PH + tid], pb1[tid])));
    // exact GELU (erf form)
    ph[tid] = 0.5f * x * (1.0f + erff(x * 0.70710678118654752f));
    __syncthreads();

    int group = idx21[i];
    int rank  = i - s_start;
    if (rank >= PADN) return;   // mode='drop'

    float* out_tok = out + ((size_t)group * PADN + rank) * CC;
    float* out_pos = out + (size_t)NS2 * PADN * CC + ((size_t)group * PADN + rank) * CC;

    for (int c = tid; c < CC; c += PH) {
        float acc = pb2[c];
#pragma unroll 8
        for (int k = 0; k < PH; k++) acc = fmaf(ph[k], P2[k * CC + c], acc);
        out_pos[c] = acc;
        out_tok[c] = decf(d_tokenc[i * CC + c]);
    }
}

// ---------------- launch ----------------
extern "C" void kernel_launch(void* const* d_in, const int* in_sizes, int n_in,
                              void* d_out, int out_size) {
    const float* X    = (const float*)d_in[0];
    const float* spc  = (const float*)d_in[1];
    const float* W1   = (const float*)d_in[2];
    const float* b1   = (const float*)d_in[3];
    const float* W2   = (const float*)d_in[4];
    const float* b2   = (const float*)d_in[5];
    const float* W3   = (const float*)d_in[6];
    const float* b3   = (const float*)d_in[7];
    const float* W4   = (const float*)d_in[8];
    const float* b4   = (const float*)d_in[9];
    const float* P1   = (const float*)d_in[10];
    const float* pb1  = (const float*)d_in[11];
    const float* P2   = (const float*)d_in[12];
    const float* pb2  = (const float*)d_in[13];
    const int* idx10  = (const int*)d_in[14];
    const int* idx21  = (const int*)d_in[15];
    float* out = (float*)d_out;

    // zero output + init encoded-max buffers
    k_pre<<<6144, 256>>>(out, out_size);

    // t1 = X @ W1 + b1
    k_mlp1<<<NPTS / 32, 128>>>(X, W1, b1);

    // f = t1 @ W2 + b2 ; segment-max -> g_enc
    k_gemm<0><<<dim3(H2 / BN, NPTS / BM), 256>>>(W2, b2, idx10);

    // decode g
    k_dec_g<<<(NS1 * H2) / 256, 256>>>();

    // h1 = relu(concat(g[idx10], f) @ W3 + b3)
    k_gemm<1><<<dim3(H3 / BN, NPTS / BM), 256>>>(W3, b3, idx10);

    // segment-max(h1 @ W4 + b4) -> tok_enc
    k_gemm<2><<<dim3(CC / BN, NPTS / BM), 256>>>(W4, b4, idx10);

    // pos embed + rank + scatter
    k_tail<<<NS1, 128>>>(spc, P1, pb1, P2, pb2, idx21, out);
}

// round 2
// speedup vs baseline: 1.1505x; 1.1505x over previous
#include <cuda_runtime.h>
#include <math.h>

#define NPTS 262144
#define NS1 4096
#define NS2 128
#define PADN 64
#define F_IN 11
#define H1 128
#define H2 256
#define H3 512
#define CC 384
#define PH 128

// ---------------- scratch (static device globals; no allocation) ----------------
__device__ float    d_f[NPTS * H2];                  // 268 MB
__device__ float    d_g[NS1 * H2];                   // 4 MB
__device__ unsigned d_genc[NS1 * H2];                // 4 MB
__device__ float    d_h1[(size_t)NPTS * H3];         // 536 MB
__device__ unsigned d_tokenc[NS1 * CC];              // 6 MB
__device__ float    d_W12[F_IN * H2];
__device__ float    d_b12[H2];

// ------------- monotonic float<->uint encoding for atomic max -------------
__device__ __forceinline__ unsigned encf(float x) {
    unsigned u = __float_as_uint(x);
    return (u & 0x80000000u) ? ~u : (u | 0x80000000u);
}
__device__ __forceinline__ float decf(unsigned u) {
    return (u & 0x80000000u) ? __uint_as_float(u & 0x7FFFFFFFu)
                             : __uint_as_float(~u);
}
#define NEG_INF_ENC 0x007FFFFFu   // encf(-inf)

__device__ __forceinline__ float f2tf32(float x) {
    unsigned r;
    asm("cvt.rna.tf32.f32 %0, %1;" : "=r"(r) : "f"(x));
    return __uint_as_float(r);
}

// ---------------- kernel: zero output + init encoded max buffers ----------------
__global__ void k_pre(float* __restrict__ out, int n) {
    int i = blockIdx.x * blockDim.x + threadIdx.x;
    int stride = gridDim.x * blockDim.x;
    for (int j = i; j < n; j += stride) out[j] = 0.0f;
    if (i < NS1 * H2) d_genc[i] = NEG_INF_ENC;
    if (i < NS1 * CC) d_tokenc[i] = NEG_INF_ENC;
}

// ---------------- kernel: W12 = W1@W2, b12 = b1@W2 + b2 (no activation between) ----------------
__global__ void k_w12(const float* __restrict__ W1, const float* __restrict__ b1,
                      const float* __restrict__ W2, const float* __restrict__ b2) {
    int c = threadIdx.x;   // 0..255
#pragma unroll 1
    for (int j = 0; j < F_IN; j++) {
        float acc = 0.0f;
#pragma unroll 8
        for (int k = 0; k < H1; k++) acc = fmaf(W1[j * H1 + k], W2[k * H2 + c], acc);
        d_W12[j * H2 + c] = acc;
    }
    float acc = b2[c];
#pragma unroll 8
    for (int k = 0; k < H1; k++) acc = fmaf(b1[k], W2[k * H2 + c], acc);
    d_b12[c] = acc;
}

// ---------------- fused: f = X @ W12 + b12 ; sorted-run segment max -> d_genc ----------------
#define F0_ROWS 256
__global__ void __launch_bounds__(256) k_fuse0(const float* __restrict__ X,
                                               const int* __restrict__ idx10) {
    __shared__ float sX[F0_ROWS * F_IN];
    __shared__ int   sS[F0_ROWS];
    int tid = threadIdx.x;
    int p0  = blockIdx.x * F0_ROWS;

    for (int q = tid; q < F0_ROWS * F_IN; q += 256) sX[q] = X[p0 * F_IN + q];
    if (tid < F0_ROWS) sS[tid] = idx10[p0 + tid];
    __syncthreads();

    float w[F_IN];
#pragma unroll
    for (int j = 0; j < F_IN; j++) w[j] = d_W12[j * H2 + tid];
    float bb = d_b12[tid];

    int prev = sS[0];
    float mx = -__int_as_float(0x7f800000);  // -inf? use -FLT_MAX style
    mx = -3.402823466e38f;

#pragma unroll 4
    for (int r = 0; r < F0_ROWS; r++) {
        float acc = bb;
#pragma unroll
        for (int j = 0; j < F_IN; j++) acc = fmaf(sX[r * F_IN + j], w[j], acc);
        d_f[(size_t)(p0 + r) * H2 + tid] = acc;
        int sid = sS[r];
        if (sid != prev) {
            atomicMax(&d_genc[prev * H2 + tid], encf(mx));
            mx = -3.402823466e38f;
            prev = sid;
        }
        mx = fmaxf(mx, acc);
    }
    atomicMax(&d_genc[prev * H2 + tid], encf(mx));
}

// ---------------- kernel: decode g_enc -> g (float) ----------------
__global__ void k_dec_g() {
    int i = blockIdx.x * blockDim.x + threadIdx.x;
    if (i < NS1 * H2) d_g[i] = decf(d_genc[i]);
}

// ---------------- TF32 tensor-core GEMM, 128x128x32, mma.m16n8k8 ----------------
// MODE 1: A = gather(concat(g[sid], f)) [N,512], B = W3 [512,512] -> relu -> d_h1
// MODE 2: A = d_h1 [N,512], B = W4 [512,384] -> +b4 -> run-scan segmax -> d_tokenc
#define BM 128
#define BN 128
#define BK 32

template <int MODE>
__global__ void __launch_bounds__(256)
k_tgemm(const float* __restrict__ B, const float* __restrict__ bias,
        const int* __restrict__ idx10) {
    constexpr int K  = H3;
    constexpr int NN = (MODE == 1) ? H3 : CC;

    // fragment-major smem: sA[mtile 8][kstep 4][lane 32 * 4 words]
    __shared__ float sA[8 * 4 * 128];
    // sB[kstep 4][ntile 16][lane 32 * 2 words]
    __shared__ float sB[4 * 16 * 64];
    __shared__ int   s_sid[BM];

    const int tid  = threadIdx.x;
    const int lane = tid & 31;
    const int warp = tid >> 5;
    const int wm   = warp >> 2;      // 0..1  -> 64 rows
    const int wn   = warp & 3;       // 0..3  -> 32 cols
    const int g    = lane >> 2;
    const int t    = lane & 3;
    const int row0 = blockIdx.y * BM;
    const int col0 = blockIdx.x * BN;

    if (tid < BM) s_sid[tid] = idx10[row0 + tid];

    float acc[4][4][4];
#pragma unroll
    for (int mt = 0; mt < 4; mt++)
#pragma unroll
        for (int nt = 0; nt < 4; nt++)
#pragma unroll
            for (int q = 0; q < 4; q++) acc[mt][nt][q] = 0.0f;

    for (int k0 = 0; k0 < K; k0 += BK) {
        __syncthreads();
        // ---- load A tile [128 rows x 32 k] into fragment-major layout ----
#pragma unroll
        for (int it = 0; it < 4; it++) {
            int q4 = tid + it * 256;          // 0..1023
            int r  = q4 >> 3;
            int c4 = q4 & 7;
            int gk = k0 + c4 * 4;
            float4 v;
            if (MODE == 1) {
                if (gk < H2)
                    v = *(const float4*)&d_g[s_sid[r] * H2 + gk];
                else
                    v = *(const float4*)&d_f[(size_t)(row0 + r) * H2 + (gk - H2)];
            } else {
                v = *(const float4*)&d_h1[(size_t)(row0 + r) * K + gk];
            }
            int mt   = r >> 4;
            int rin  = r & 15;
            int gg   = rin & 7;
            int hi   = rin >> 3;
            int ks   = c4 >> 1;
            int half = (c4 & 1) ? 2 : 0;
            int base = ((mt * 4 + ks) << 7) + gg * 16 + half + hi;
            sA[base + 0]  = f2tf32(v.x);
            sA[base + 4]  = f2tf32(v.y);
            sA[base + 8]  = f2tf32(v.z);
            sA[base + 12] = f2tf32(v.w);
        }
        // ---- load B tile [32 k x 128 n] into fragment-major layout ----
#pragma unroll
        for (int it = 0; it < 4; it++) {
            int q4 = tid + it * 256;
            int kr = q4 >> 5;
            int c4 = q4 & 31;
            float4 v = *(const float4*)&B[(k0 + kr) * NN + col0 + c4 * 4];
            int ks  = kr >> 3;
            int kin = kr & 7;
            int tt  = kin & 3;
            int j   = (kin >= 4) ? 1 : 0;
            int nt  = c4 >> 1;
            int gb  = (c4 & 1) * 4;           // n base within 8-col tile
            int b0  = ((ks * 16 + nt) << 6) + tt * 2 + j;
            sB[b0 + (gb + 0) * 8] = f2tf32(v.x);
            sB[b0 + (gb + 1) * 8] = f2tf32(v.y);
            sB[b0 + (gb + 2) * 8] = f2tf32(v.z);
            sB[b0 + (gb + 3) * 8] = f2tf32(v.w);
        }
        __syncthreads();

        // ---- compute: 4 k-steps of m16n8k8 ----
#pragma unroll
        for (int ks = 0; ks < 4; ks++) {
            unsigned a[4][4];
            unsigned b[4][2];
#pragma unroll
            for (int mt = 0; mt < 4; mt++) {
                float4 va = *(const float4*)&sA[(((wm * 4 + mt) * 4 + ks) << 7) + lane * 4];
                a[mt][0] = __float_as_uint(va.x);
                a[mt][1] = __float_as_uint(va.y);
                a[mt][2] = __float_as_uint(va.z);
                a[mt][3] = __float_as_uint(va.w);
            }
#pragma unroll
            for (int nt = 0; nt < 4; nt++) {
                float2 vb = *(const float2*)&sB[((ks * 16 + wn * 4 + nt) << 6) + lane * 2];
                b[nt][0] = __float_as_uint(vb.x);
                b[nt][1] = __float_as_uint(vb.y);
            }
#pragma unroll
            for (int mt = 0; mt < 4; mt++)
#pragma unroll
                for (int nt = 0; nt < 4; nt++) {
                    asm volatile(
                        "mma.sync.aligned.m16n8k8.row.col.f32.tf32.tf32.f32 "
                        "{%0,%1,%2,%3}, {%4,%5,%6,%7}, {%8,%9}, {%0,%1,%2,%3};"
                        : "+f"(acc[mt][nt][0]), "+f"(acc[mt][nt][1]),
                          "+f"(acc[mt][nt][2]), "+f"(acc[mt][nt][3])
                        : "r"(a[mt][0]), "r"(a[mt][1]), "r"(a[mt][2]), "r"(a[mt][3]),
                          "r"(b[nt][0]), "r"(b[nt][1]));
                }
        }
    }

    // ---- epilogue ----
    if (MODE == 1) {
#pragma unroll
        for (int mt = 0; mt < 4; mt++) {
            int row = row0 + wm * 64 + mt * 16 + g;
#pragma unroll
            for (int nt = 0; nt < 4; nt++) {
                int col = col0 + wn * 32 + nt * 8 + t * 2;
                float b0v = bias[col], b1v = bias[col + 1];
                float2 v0, v1;
                v0.x = fmaxf(acc[mt][nt][0] + b0v, 0.0f);
                v0.y = fmaxf(acc[mt][nt][1] + b1v, 0.0f);
                v1.x = fmaxf(acc[mt][nt][2] + b0v, 0.0f);
                v1.y = fmaxf(acc[mt][nt][3] + b1v, 0.0f);
                *(float2*)&d_h1[(size_t)row * H3 + col]       = v0;
                *(float2*)&d_h1[(size_t)(row + 8) * H3 + col] = v1;
            }
        }
    } else {
        // rows this thread owns, in increasing order: wm*64 + mt*16 + hi*8 + g
        int sids[8];
#pragma unroll
        for (int mt = 0; mt < 4; mt++)
#pragma unroll
            for (int hi = 0; hi < 2; hi++)
                sids[mt * 2 + hi] = s_sid[wm * 64 + mt * 16 + hi * 8 + g];
#pragma unroll
        for (int nt = 0; nt < 4; nt++) {
#pragma unroll
            for (int p = 0; p < 2; p++) {
                int col = col0 + wn * 32 + nt * 8 + t * 2 + p;
                float bb = bias[col];
                int prev = sids[0];
                float mx = -3.402823466e38f;
#pragma unroll
                for (int mt = 0; mt < 4; mt++)
#pragma unroll
                    for (int hi = 0; hi < 2; hi++) {
                        int sid = sids[mt * 2 + hi];
                        float v = acc[mt][nt][hi * 2 + p] + bb;
                        if (sid != prev) {
                            atomicMax(&d_tokenc[prev * CC + col], encf(mx));
                            mx = -3.402823466e38f;
                            prev = sid;
                        }
                        mx = fmaxf(mx, v);
                    }
                atomicMax(&d_tokenc[prev * CC + col], encf(mx));
            }
        }
    }
}

// ---------------- kernel: pos embed + rank + scatter both outputs ----------------
__global__ void k_tail(const float* __restrict__ spc,
                       const float* __restrict__ P1, const float* __restrict__ pb1,
                       const float* __restrict__ P2, const float* __restrict__ pb2,
                       const int* __restrict__ idx21,
                       float* __restrict__ out) {
    int i   = blockIdx.x;      // superpoint-1 index
    int tid = threadIdx.x;     // 128 threads
    __shared__ float ph[PH];
    __shared__ int s_start;

    if (tid == 0) {
        int v = idx21[i];
        int lo = 0, hi = NS1;
        while (lo < hi) {
            int mid = (lo + hi) >> 1;
            if (idx21[mid] < v) lo = mid + 1; else hi = mid;
        }
        s_start = lo;
    }

    float c0 = spc[i * 3 + 0], c1 = spc[i * 3 + 1], c2 = spc[i * 3 + 2];
    float x = fmaf(c0, P1[tid], fmaf(c1, P1[PH + tid], fmaf(c2, P1[2 * PH + tid], pb1[tid])));
    ph[tid] = 0.5f * x * (1.0f + erff(x * 0.70710678118654752f));
    __syncthreads();

    int group = idx21[i];
    int rank  = i - s_start;
    if (rank >= PADN) return;   // mode='drop'

    float* out_tok = out + ((size_t)group * PADN + rank) * CC;
    float* out_pos = out + (size_t)NS2 * PADN * CC + ((size_t)group * PADN + rank) * CC;

    for (int c = tid; c < CC; c += PH) {
        float acc = pb2[c];
#pragma unroll 8
        for (int k = 0; k < PH; k++) acc = fmaf(ph[k], P2[k * CC + c], acc);
        out_pos[c] = acc;
        out_tok[c] = decf(d_tokenc[i * CC + c]);
    }
}

// ---------------- launch ----------------
extern "C" void kernel_launch(void* const* d_in, const int* in_sizes, int n_in,
                              void* d_out, int out_size) {
    const float* X    = (const float*)d_in[0];
    const float* spc  = (const float*)d_in[1];
    const float* W1   = (const float*)d_in[2];
    const float* b1   = (const float*)d_in[3];
    const float* W2   = (const float*)d_in[4];
    const float* b2   = (const float*)d_in[5];
    const float* W3   = (const float*)d_in[6];
    const float* b3   = (const float*)d_in[7];
    const float* W4   = (const float*)d_in[8];
    const float* b4   = (const float*)d_in[9];
    const float* P1   = (const float*)d_in[10];
    const float* pb1  = (const float*)d_in[11];
    const float* P2   = (const float*)d_in[12];
    const float* pb2  = (const float*)d_in[13];
    const int* idx10  = (const int*)d_in[14];
    const int* idx21  = (const int*)d_in[15];
    float* out = (float*)d_out;

    // zero output + init encoded-max buffers
    k_pre<<<6144, 256>>>(out, out_size);

    // collapse W1/W2 (no activation between them)
    k_w12<<<1, H2>>>(W1, b1, W2, b2);

    // f = X @ W12 + b12 ; segment-max -> g_enc (sorted-run scan, few atomics)
    k_fuse0<<<NPTS / F0_ROWS, 256>>>(X, idx10);

    // decode g
    k_dec_g<<<(NS1 * H2) / 256, 256>>>();

    // h1 = relu(concat(g[idx10], f) @ W3 + b3)   [tf32 tensor cores]
    k_tgemm<1><<<dim3(H3 / BN, NPTS / BM), 256>>>(W3, b3, idx10);

    // segment-max(h1 @ W4 + b4) -> tok_enc       [tf32 tensor cores]
    k_tgemm<2><<<dim3(CC / BN, NPTS / BM), 256>>>(W4, b4, idx10);

    // pos embed + rank + scatter
    k_tail<<<NS1, 128>>>(spc, P1, pb1, P2, pb2, idx21, out);
}